// round 3
// baseline (speedup 1.0000x reference)
#include <cuda_runtime.h>
#include <cstdint>
#include <cstddef>

#define TSTEPS 512
#define BATCH  64
#define HID    1024
#define G3     3072
#define MROWS  (TSTEPS * BATCH)   // 32768

// ---- scratch (device globals; no runtime allocation allowed) ----
__device__ float g_gi[(size_t)MROWS * G3];   // 384 MB
__device__ float g_y0[(size_t)MROWS * HID];  // 128 MB
__device__ float g_ha[BATCH * HID];
__device__ float g_hb[BATCH * HID];
__device__ unsigned g_cnt[2];                // grid-barrier parity counters

// ---- helpers ----
__device__ __forceinline__ uint32_t f2tf(float f) {
    uint32_t u;
    asm("cvt.rna.tf32.f32 %0, %1;" : "=r"(u) : "f"(f));
    return u;
}

__device__ __forceinline__ void mma_tf32(float d[4],
    uint32_t a0, uint32_t a1, uint32_t a2, uint32_t a3,
    uint32_t b0, uint32_t b1)
{
    asm volatile(
        "mma.sync.aligned.m16n8k8.row.col.f32.tf32.tf32.f32 "
        "{%0,%1,%2,%3},{%4,%5,%6,%7},{%8,%9},{%0,%1,%2,%3};"
        : "+f"(d[0]), "+f"(d[1]), "+f"(d[2]), "+f"(d[3])
        : "r"(a0), "r"(a1), "r"(a2), "r"(a3), "r"(b0), "r"(b1));
}

__device__ __forceinline__ float sigmoidf_(float x) {
    return 1.0f / (1.0f + __expf(-x));
}

// ============================================================================
// Big GEMM: C[M,N] = A[M,K] @ W[N,K]^T + bias[N]   (tf32 MMA, fp32 accum)
// ============================================================================
#define GBM 128
#define GBN 64
#define GBK 16
#define GSTR 20

__global__ __launch_bounds__(256) void gemm_tn_bias(
    const float* __restrict__ A,
    const float* __restrict__ W,
    const float* __restrict__ bias,
    float* __restrict__ C,
    int K, int N)
{
    __shared__ uint32_t As[2][GBM * GSTR];
    __shared__ uint32_t Bs[2][GBN * GSTR];

    const int t    = threadIdx.x;
    const int bm   = blockIdx.y, bn = blockIdx.x;
    const int warp = t >> 5, lane = t & 31;
    const int wm   = warp >> 1, wn = warp & 1;
    const int g    = lane >> 2, tg = lane & 3;

    const float* Ab = A + (size_t)bm * GBM * K;
    const float* Wb = W + (size_t)bn * GBN * K;

    const int lr = t >> 2;
    const int lq = (t & 3) * 4;

    float acc[2][4][4];
#pragma unroll
    for (int i = 0; i < 2; ++i)
#pragma unroll
        for (int j = 0; j < 4; ++j)
#pragma unroll
            for (int k = 0; k < 4; ++k) acc[i][j][k] = 0.0f;

    float4 ra0, ra1, rw0;

    ra0 = *(const float4*)(Ab + (size_t)lr * K + lq);
    ra1 = *(const float4*)(Ab + (size_t)(lr + 64) * K + lq);
    rw0 = *(const float4*)(Wb + (size_t)lr * K + lq);
    {
        uint32_t* as = As[0]; uint32_t* bs = Bs[0];
        as[lr * GSTR + lq + 0] = f2tf(ra0.x);
        as[lr * GSTR + lq + 1] = f2tf(ra0.y);
        as[lr * GSTR + lq + 2] = f2tf(ra0.z);
        as[lr * GSTR + lq + 3] = f2tf(ra0.w);
        as[(lr + 64) * GSTR + lq + 0] = f2tf(ra1.x);
        as[(lr + 64) * GSTR + lq + 1] = f2tf(ra1.y);
        as[(lr + 64) * GSTR + lq + 2] = f2tf(ra1.z);
        as[(lr + 64) * GSTR + lq + 3] = f2tf(ra1.w);
        bs[lr * GSTR + lq + 0] = f2tf(rw0.x);
        bs[lr * GSTR + lq + 1] = f2tf(rw0.y);
        bs[lr * GSTR + lq + 2] = f2tf(rw0.z);
        bs[lr * GSTR + lq + 3] = f2tf(rw0.w);
    }

    const int NCH = K / GBK;
    for (int c = 0; c < NCH; ++c) {
        __syncthreads();
        const int b = c & 1;
        if (c + 1 < NCH) {
            const int kg = (c + 1) * GBK;
            ra0 = *(const float4*)(Ab + (size_t)lr * K + kg + lq);
            ra1 = *(const float4*)(Ab + (size_t)(lr + 64) * K + kg + lq);
            rw0 = *(const float4*)(Wb + (size_t)lr * K + kg + lq);
        }
#pragma unroll
        for (int ks = 0; ks < 2; ++ks) {
            const int k0 = ks * 8;
            uint32_t af[2][4], bf[4][2];
#pragma unroll
            for (int mt = 0; mt < 2; ++mt) {
                const int rb = wm * 32 + mt * 16;
                af[mt][0] = As[b][(rb + g    ) * GSTR + k0 + tg    ];
                af[mt][1] = As[b][(rb + g + 8) * GSTR + k0 + tg    ];
                af[mt][2] = As[b][(rb + g    ) * GSTR + k0 + tg + 4];
                af[mt][3] = As[b][(rb + g + 8) * GSTR + k0 + tg + 4];
            }
#pragma unroll
            for (int nt = 0; nt < 4; ++nt) {
                const int nb = wn * 32 + nt * 8;
                bf[nt][0] = Bs[b][(nb + g) * GSTR + k0 + tg    ];
                bf[nt][1] = Bs[b][(nb + g) * GSTR + k0 + tg + 4];
            }
#pragma unroll
            for (int mt = 0; mt < 2; ++mt)
#pragma unroll
                for (int nt = 0; nt < 4; ++nt)
                    mma_tf32(acc[mt][nt],
                             af[mt][0], af[mt][1], af[mt][2], af[mt][3],
                             bf[nt][0], bf[nt][1]);
        }
        if (c + 1 < NCH) {
            const int nb2 = (c + 1) & 1;
            uint32_t* as = As[nb2]; uint32_t* bs = Bs[nb2];
            as[lr * GSTR + lq + 0] = f2tf(ra0.x);
            as[lr * GSTR + lq + 1] = f2tf(ra0.y);
            as[lr * GSTR + lq + 2] = f2tf(ra0.z);
            as[lr * GSTR + lq + 3] = f2tf(ra0.w);
            as[(lr + 64) * GSTR + lq + 0] = f2tf(ra1.x);
            as[(lr + 64) * GSTR + lq + 1] = f2tf(ra1.y);
            as[(lr + 64) * GSTR + lq + 2] = f2tf(ra1.z);
            as[(lr + 64) * GSTR + lq + 3] = f2tf(ra1.w);
            bs[lr * GSTR + lq + 0] = f2tf(rw0.x);
            bs[lr * GSTR + lq + 1] = f2tf(rw0.y);
            bs[lr * GSTR + lq + 2] = f2tf(rw0.z);
            bs[lr * GSTR + lq + 3] = f2tf(rw0.w);
        }
    }

#pragma unroll
    for (int mt = 0; mt < 2; ++mt) {
        const int row = bm * GBM + wm * 32 + mt * 16 + g;
#pragma unroll
        for (int nt = 0; nt < 4; ++nt) {
            const int col = bn * GBN + wn * 32 + nt * 8 + tg * 2;
            const float b0 = bias[col], b1 = bias[col + 1];
            float2 v0 = make_float2(acc[mt][nt][0] + b0, acc[mt][nt][1] + b1);
            float2 v1 = make_float2(acc[mt][nt][2] + b0, acc[mt][nt][3] + b1);
            *(float2*)(C + (size_t)row * N + col)       = v0;
            *(float2*)(C + (size_t)(row + 8) * N + col) = v1;
        }
    }
}

// ============================================================================
// Persistent recurrence kernel: ONE launch runs all 512 timesteps of a layer.
// 128 blocks (1/SM, guaranteed co-resident), 256 threads (8 warps).
// Block j owns h-columns [8j, 8j+8) -> 24 w_hh rows, cached in smem as tf32
// for the whole layer. Per step: stage h (ping-pong, __ldcg) into double-
// buffered smem chunks; warps = 2 m-groups x 4 k-quarters; k-partial sums
// reduced via smem; warps 0-1 apply gates and write h/y; grid barrier.
// ============================================================================
#define RBLK 128
#define RTHR 256
#define RCOLS 8
#define WSTR 1028          // 24 x 1028 u32 tf32 w-slice (conflict-free)
#define HSTR 36            // 64 x 36 u32 per 32-k chunk (conflict-free)
#define HCHUNK_U32 (64 * HSTR)             // 2304
#define WS_U32 (24 * WSTR)                 // 24672
#define RSM_U32 (WS_U32 + 2 * 4 * HCHUNK_U32)  // 43104 u32 = 172416 B

__device__ __forceinline__ void grid_bar(int t, unsigned nb) {
    __syncthreads();
    if (threadIdx.x == 0) {
        const unsigned tgt = (unsigned)(t / 2 + 1) * nb;
        unsigned* ctr = &g_cnt[t & 1];
        __threadfence();
        atomicAdd(ctr, 1u);
        unsigned v;
        do {
            asm volatile("ld.acquire.gpu.u32 %0, [%1];"
                         : "=r"(v) : "l"(ctr) : "memory");
        } while (v < tgt);
    }
    __syncthreads();
}

__global__ void __launch_bounds__(RTHR, 1) gru_rec(
    const float* __restrict__ gi_base,  // [T][64][3072] (b_ih folded in)
    const float* __restrict__ h0,       // [64][1024] initial hidden
    const float* __restrict__ w_hh,     // [3072][1024]
    const float* __restrict__ b_hh,     // [3072]
    float* __restrict__ hbuf0,
    float* __restrict__ hbuf1,
    float* __restrict__ y,              // [T][64][1024]
    float* __restrict__ hn)             // [64][1024] final state
{
    extern __shared__ uint32_t sm[];
    uint32_t* Ws = sm;
    uint32_t* Hs = sm + WS_U32;
    float* red   = (float*)(sm + WS_U32);   // reused after MMA phase

    const int tid  = threadIdx.x;
    const int warp = tid >> 5, lane = tid & 31;
    const int g    = lane >> 2, tg = lane & 3;
    const int mg   = warp & 1;       // m-group: rows [mg*32, mg*32+32)
    const int kq   = warp >> 1;      // k-quarter: k in [kq*256, kq*256+256)
    const int j0   = blockIdx.x * RCOLS;
    const unsigned nb = gridDim.x;

    // ---- cache w_hh slice (24 rows x 1024) in smem as tf32, once ----
#pragma unroll 4
    for (int j = 0; j < 24; ++j) {
        const int u = tid + j * RTHR;      // 0..6143 (float4 units)
        const int r = u >> 8;              // slice row 0..23
        const int q = u & 255;             // f4 within row
        const int grow = (r >> 3) * HID + j0 + (r & 7);
        float4 v = *(const float4*)(w_hh + (size_t)grow * HID + q * 4);
        uint32_t* dst = Ws + r * WSTR + q * 4;
        dst[0] = f2tf(v.x); dst[1] = f2tf(v.y);
        dst[2] = f2tf(v.z); dst[3] = f2tf(v.w);
    }

    // biases (used by warps 0-1 in the gate phase)
    const int col = j0 + tg * 2;
    const float br0 = b_hh[col],           br1 = b_hh[col + 1];
    const float bz0 = b_hh[HID + col],     bz1 = b_hh[HID + col + 1];
    const float bn0 = b_hh[2 * HID + col], bn1 = b_hh[2 * HID + col + 1];

    __syncthreads();

    for (int t = 0; t < TSTEPS; ++t) {
        const float* h_in = (t == 0) ? h0 : ((t & 1) ? hbuf0 : hbuf1);
        float* h_out = (t & 1) ? hbuf1 : hbuf0;

        float acc[2][3][4];
#pragma unroll
        for (int a = 0; a < 2; ++a)
#pragma unroll
            for (int b = 0; b < 3; ++b)
#pragma unroll
                for (int d = 0; d < 4; ++d) acc[a][b][d] = 0.0f;

        float4 rh[8];

        // prologue: load chunk 0 (one 32-k chunk per quarter) and stage
#pragma unroll
        for (int j = 0; j < 8; ++j) {
            const int u = tid + j * RTHR;          // 0..2047
            const int qu = u >> 9;                 // quarter
            const int v2 = u & 511;
            const int row = v2 >> 3, q8 = v2 & 7;
            const int gk = qu * 256 + q8 * 4;
            rh[j] = __ldcg((const float4*)(h_in + row * HID + gk));
        }
        {
#pragma unroll
            for (int j = 0; j < 8; ++j) {
                const int u = tid + j * RTHR;
                const int qu = u >> 9;
                const int v2 = u & 511;
                const int row = v2 >> 3, q8 = v2 & 7;
                uint4 pv = make_uint4(f2tf(rh[j].x), f2tf(rh[j].y),
                                      f2tf(rh[j].z), f2tf(rh[j].w));
                *(uint4*)(Hs + (0 * 4 + qu) * HCHUNK_U32 + row * HSTR + q8 * 4) = pv;
            }
        }

        // 8 chunk iterations (each chunk = 32 k per quarter), double-buffered
        for (int c = 0; c < 8; ++c) {
            __syncthreads();
            if (c + 1 < 8) {
#pragma unroll
                for (int j = 0; j < 8; ++j) {
                    const int u = tid + j * RTHR;
                    const int qu = u >> 9;
                    const int v2 = u & 511;
                    const int row = v2 >> 3, q8 = v2 & 7;
                    const int gk = qu * 256 + (c + 1) * 32 + q8 * 4;
                    rh[j] = __ldcg((const float4*)(h_in + row * HID + gk));
                }
            }
            const uint32_t* Hq = Hs + ((c & 1) * 4 + kq) * HCHUNK_U32;
#pragma unroll
            for (int ks = 0; ks < 4; ++ks) {
                const int k0 = ks * 8;
                uint32_t a[2][4];
#pragma unroll
                for (int mt = 0; mt < 2; ++mt) {
                    const int rb = mg * 32 + mt * 16;
                    a[mt][0] = Hq[(rb + g    ) * HSTR + k0 + tg    ];
                    a[mt][1] = Hq[(rb + g + 8) * HSTR + k0 + tg    ];
                    a[mt][2] = Hq[(rb + g    ) * HSTR + k0 + tg + 4];
                    a[mt][3] = Hq[(rb + g + 8) * HSTR + k0 + tg + 4];
                }
                const int wk = kq * 256 + c * 32 + k0 + tg;
#pragma unroll
                for (int nt = 0; nt < 3; ++nt) {
                    const uint32_t b0 = Ws[(nt * 8 + g) * WSTR + wk    ];
                    const uint32_t b1 = Ws[(nt * 8 + g) * WSTR + wk + 4];
                    mma_tf32(acc[0][nt], a[0][0], a[0][1], a[0][2], a[0][3], b0, b1);
                    mma_tf32(acc[1][nt], a[1][0], a[1][1], a[1][2], a[1][3], b0, b1);
                }
            }
            if (c + 1 < 8) {
#pragma unroll
                for (int j = 0; j < 8; ++j) {
                    const int u = tid + j * RTHR;
                    const int qu = u >> 9;
                    const int v2 = u & 511;
                    const int row = v2 >> 3, q8 = v2 & 7;
                    uint4 pv = make_uint4(f2tf(rh[j].x), f2tf(rh[j].y),
                                          f2tf(rh[j].z), f2tf(rh[j].w));
                    *(uint4*)(Hs + (((c + 1) & 1) * 4 + qu) * HCHUNK_U32
                              + row * HSTR + q8 * 4) = pv;
                }
            }
        }

        // ---- reduce k-quarter partial sums (reuse Hs region) ----
        __syncthreads();
        if (kq != 0) {
            float* dst = red + (size_t)(((kq - 1) * 2 + mg) * 32 + lane) * 25;
#pragma unroll
            for (int mt = 0; mt < 2; ++mt)
#pragma unroll
                for (int nt = 0; nt < 3; ++nt)
#pragma unroll
                    for (int d = 0; d < 4; ++d)
                        dst[mt * 12 + nt * 4 + d] = acc[mt][nt][d];
        }
        __syncthreads();

        if (kq == 0) {
#pragma unroll
            for (int q = 1; q < 4; ++q) {
                const float* src = red + (size_t)(((q - 1) * 2 + mg) * 32 + lane) * 25;
#pragma unroll
                for (int mt = 0; mt < 2; ++mt)
#pragma unroll
                    for (int nt = 0; nt < 3; ++nt)
#pragma unroll
                        for (int d = 0; d < 4; ++d)
                            acc[mt][nt][d] += src[mt * 12 + nt * 4 + d];
            }

            // ---- gates ----
            const float* gi_t = gi_base + (size_t)t * BATCH * G3;
            float* y_t = y + (size_t)t * BATCH * HID;
#pragma unroll
            for (int mt = 0; mt < 2; ++mt) {
#pragma unroll
                for (int rr = 0; rr < 2; ++rr) {
                    const int m = mg * 32 + mt * 16 + g + rr * 8;
                    const float* gim = gi_t + (size_t)m * G3;
                    float2 ir  = *(const float2*)(gim + col);
                    float2 iz  = *(const float2*)(gim + HID + col);
                    float2 in2 = *(const float2*)(gim + 2 * HID + col);
                    float2 hp  = __ldcg((const float2*)(h_in + m * HID + col));

                    const float gr0 = acc[mt][0][rr * 2 + 0] + br0;
                    const float gr1 = acc[mt][0][rr * 2 + 1] + br1;
                    const float gz0 = acc[mt][1][rr * 2 + 0] + bz0;
                    const float gz1 = acc[mt][1][rr * 2 + 1] + bz1;
                    const float gn0 = acc[mt][2][rr * 2 + 0] + bn0;
                    const float gn1 = acc[mt][2][rr * 2 + 1] + bn1;

                    const float r0 = sigmoidf_(ir.x + gr0);
                    const float r1 = sigmoidf_(ir.y + gr1);
                    const float z0 = sigmoidf_(iz.x + gz0);
                    const float z1 = sigmoidf_(iz.y + gz1);
                    const float n0 = tanhf(in2.x + r0 * gn0);
                    const float n1 = tanhf(in2.y + r1 * gn1);

                    float2 hv = make_float2((1.0f - z0) * n0 + z0 * hp.x,
                                            (1.0f - z1) * n1 + z1 * hp.y);
                    *(float2*)(h_out + m * HID + col) = hv;
                    *(float2*)(y_t + m * HID + col)   = hv;
                    if (t == TSTEPS - 1)
                        *(float2*)(hn + m * HID + col) = hv;
                }
            }
        }

        grid_bar(t, nb);
    }
}

__global__ void bar_reset() {
    g_cnt[0] = 0u;
    g_cnt[1] = 0u;
}

// ============================================================================
// Launcher: 6-node graph: gemm -> rec(layer0) -> reset -> gemm -> rec(layer1)
// -> reset. Fully capturable; no memcpys; tiny graph => no 2MB upload leak.
// ============================================================================
extern "C" void kernel_launch(void* const* d_in, const int* in_sizes, int n_in,
                              void* d_out, int out_size)
{
    const float* x      = (const float*)d_in[0];
    const float* hx     = (const float*)d_in[1];
    const float* w_ih_0 = (const float*)d_in[2];
    const float* w_hh_0 = (const float*)d_in[3];
    const float* b_ih_0 = (const float*)d_in[4];
    const float* b_hh_0 = (const float*)d_in[5];
    const float* w_ih_1 = (const float*)d_in[6];
    const float* w_hh_1 = (const float*)d_in[7];
    const float* b_ih_1 = (const float*)d_in[8];
    const float* b_hh_1 = (const float*)d_in[9];

    float* out = (float*)d_out;
    float* hn0 = out + (size_t)MROWS * HID;
    float* hn1 = hn0 + (size_t)BATCH * HID;

    float *gi, *y0, *ha, *hb;
    cudaGetSymbolAddress((void**)&gi, g_gi);
    cudaGetSymbolAddress((void**)&y0, g_y0);
    cudaGetSymbolAddress((void**)&ha, g_ha);
    cudaGetSymbolAddress((void**)&hb, g_hb);

    cudaFuncSetAttribute(gru_rec, cudaFuncAttributeMaxDynamicSharedMemorySize,
                         RSM_U32 * 4);

    dim3 ggrid(G3 / GBN, MROWS / GBM);  // (48, 256)

    // ---- layer 0 ----
    gemm_tn_bias<<<ggrid, 256>>>(x, w_ih_0, b_ih_0, gi, HID, G3);
    gru_rec<<<RBLK, RTHR, RSM_U32 * 4>>>(gi, hx, w_hh_0, b_hh_0,
                                         ha, hb, y0, hn0);
    bar_reset<<<1, 1>>>();

    // ---- layer 1 ----
    gemm_tn_bias<<<ggrid, 256>>>(y0, w_ih_1, b_ih_1, gi, HID, G3);
    gru_rec<<<RBLK, RTHR, RSM_U32 * 4>>>(gi, hx + (size_t)BATCH * HID,
                                         w_hh_1, b_hh_1,
                                         ha, hb, out, hn1);
    bar_reset<<<1, 1>>>();

    (void)in_sizes; (void)n_in; (void)out_size;
}

// round 4
// speedup vs baseline: 1.2207x; 1.2207x over previous
#include <cuda_runtime.h>
#include <cstdint>
#include <cstddef>

#define TSTEPS 512
#define BATCH  64
#define HID    1024
#define G3     3072
#define MROWS  (TSTEPS * BATCH)   // 32768

// ---- scratch (device globals; no runtime allocation allowed) ----
__device__ float g_gi[(size_t)MROWS * G3];   // 384 MB
__device__ float g_y0[(size_t)MROWS * HID];  // 128 MB
__device__ float g_ha[BATCH * HID];
__device__ float g_hb[BATCH * HID];
__device__ unsigned g_cnt[2];                // grid-barrier parity counters

// ---- helpers ----
__device__ __forceinline__ uint32_t f2tf(float f) {
    uint32_t u;
    asm("cvt.rna.tf32.f32 %0, %1;" : "=r"(u) : "f"(f));
    return u;
}

__device__ __forceinline__ void mma_tf32(float d[4],
    uint32_t a0, uint32_t a1, uint32_t a2, uint32_t a3,
    uint32_t b0, uint32_t b1)
{
    asm volatile(
        "mma.sync.aligned.m16n8k8.row.col.f32.tf32.tf32.f32 "
        "{%0,%1,%2,%3},{%4,%5,%6,%7},{%8,%9},{%0,%1,%2,%3};"
        : "+f"(d[0]), "+f"(d[1]), "+f"(d[2]), "+f"(d[3])
        : "r"(a0), "r"(a1), "r"(a2), "r"(a3), "r"(b0), "r"(b1));
}

__device__ __forceinline__ float frcp(float x) {
    float r; asm("rcp.approx.f32 %0, %1;" : "=f"(r) : "f"(x)); return r;
}
__device__ __forceinline__ float fex2(float x) {
    float r; asm("ex2.approx.f32 %0, %1;" : "=f"(r) : "f"(x)); return r;
}
// sigmoid(x) = 1 / (1 + 2^(-x*log2e))
__device__ __forceinline__ float fsig(float x) {
    return frcp(1.0f + fex2(-1.4426950408889634f * x));
}
// tanh(x) = 1 - 2/(e^(2x)+1)   (accurate to ~1e-6, overflow-safe)
__device__ __forceinline__ float ftanh(float x) {
    return 1.0f - 2.0f * frcp(1.0f + fex2(2.8853900817779268f * x));
}

// ============================================================================
// Big GEMM: C[M,N] = A[M,K] @ W[N,K]^T + bias[N]   (tf32 MMA, fp32 accum)
// ============================================================================
#define GBM 128
#define GBN 64
#define GBK 16
#define GSTR 20

__global__ __launch_bounds__(256) void gemm_tn_bias(
    const float* __restrict__ A,
    const float* __restrict__ W,
    const float* __restrict__ bias,
    float* __restrict__ C,
    int K, int N)
{
    __shared__ uint32_t As[2][GBM * GSTR];
    __shared__ uint32_t Bs[2][GBN * GSTR];

    const int t    = threadIdx.x;
    const int bm   = blockIdx.y, bn = blockIdx.x;
    const int warp = t >> 5, lane = t & 31;
    const int wm   = warp >> 1, wn = warp & 1;
    const int g    = lane >> 2, tg = lane & 3;

    const float* Ab = A + (size_t)bm * GBM * K;
    const float* Wb = W + (size_t)bn * GBN * K;

    const int lr = t >> 2;
    const int lq = (t & 3) * 4;

    float acc[2][4][4];
#pragma unroll
    for (int i = 0; i < 2; ++i)
#pragma unroll
        for (int j = 0; j < 4; ++j)
#pragma unroll
            for (int k = 0; k < 4; ++k) acc[i][j][k] = 0.0f;

    float4 ra0, ra1, rw0;

    ra0 = *(const float4*)(Ab + (size_t)lr * K + lq);
    ra1 = *(const float4*)(Ab + (size_t)(lr + 64) * K + lq);
    rw0 = *(const float4*)(Wb + (size_t)lr * K + lq);
    {
        uint32_t* as = As[0]; uint32_t* bs = Bs[0];
        as[lr * GSTR + lq + 0] = f2tf(ra0.x);
        as[lr * GSTR + lq + 1] = f2tf(ra0.y);
        as[lr * GSTR + lq + 2] = f2tf(ra0.z);
        as[lr * GSTR + lq + 3] = f2tf(ra0.w);
        as[(lr + 64) * GSTR + lq + 0] = f2tf(ra1.x);
        as[(lr + 64) * GSTR + lq + 1] = f2tf(ra1.y);
        as[(lr + 64) * GSTR + lq + 2] = f2tf(ra1.z);
        as[(lr + 64) * GSTR + lq + 3] = f2tf(ra1.w);
        bs[lr * GSTR + lq + 0] = f2tf(rw0.x);
        bs[lr * GSTR + lq + 1] = f2tf(rw0.y);
        bs[lr * GSTR + lq + 2] = f2tf(rw0.z);
        bs[lr * GSTR + lq + 3] = f2tf(rw0.w);
    }

    const int NCH = K / GBK;
    for (int c = 0; c < NCH; ++c) {
        __syncthreads();
        const int b = c & 1;
        if (c + 1 < NCH) {
            const int kg = (c + 1) * GBK;
            ra0 = *(const float4*)(Ab + (size_t)lr * K + kg + lq);
            ra1 = *(const float4*)(Ab + (size_t)(lr + 64) * K + kg + lq);
            rw0 = *(const float4*)(Wb + (size_t)lr * K + kg + lq);
        }
#pragma unroll
        for (int ks = 0; ks < 2; ++ks) {
            const int k0 = ks * 8;
            uint32_t af[2][4], bf[4][2];
#pragma unroll
            for (int mt = 0; mt < 2; ++mt) {
                const int rb = wm * 32 + mt * 16;
                af[mt][0] = As[b][(rb + g    ) * GSTR + k0 + tg    ];
                af[mt][1] = As[b][(rb + g + 8) * GSTR + k0 + tg    ];
                af[mt][2] = As[b][(rb + g    ) * GSTR + k0 + tg + 4];
                af[mt][3] = As[b][(rb + g + 8) * GSTR + k0 + tg + 4];
            }
#pragma unroll
            for (int nt = 0; nt < 4; ++nt) {
                const int nb = wn * 32 + nt * 8;
                bf[nt][0] = Bs[b][(nb + g) * GSTR + k0 + tg    ];
                bf[nt][1] = Bs[b][(nb + g) * GSTR + k0 + tg + 4];
            }
#pragma unroll
            for (int mt = 0; mt < 2; ++mt)
#pragma unroll
                for (int nt = 0; nt < 4; ++nt)
                    mma_tf32(acc[mt][nt],
                             af[mt][0], af[mt][1], af[mt][2], af[mt][3],
                             bf[nt][0], bf[nt][1]);
        }
        if (c + 1 < NCH) {
            const int nb2 = (c + 1) & 1;
            uint32_t* as = As[nb2]; uint32_t* bs = Bs[nb2];
            as[lr * GSTR + lq + 0] = f2tf(ra0.x);
            as[lr * GSTR + lq + 1] = f2tf(ra0.y);
            as[lr * GSTR + lq + 2] = f2tf(ra0.z);
            as[lr * GSTR + lq + 3] = f2tf(ra0.w);
            as[(lr + 64) * GSTR + lq + 0] = f2tf(ra1.x);
            as[(lr + 64) * GSTR + lq + 1] = f2tf(ra1.y);
            as[(lr + 64) * GSTR + lq + 2] = f2tf(ra1.z);
            as[(lr + 64) * GSTR + lq + 3] = f2tf(ra1.w);
            bs[lr * GSTR + lq + 0] = f2tf(rw0.x);
            bs[lr * GSTR + lq + 1] = f2tf(rw0.y);
            bs[lr * GSTR + lq + 2] = f2tf(rw0.z);
            bs[lr * GSTR + lq + 3] = f2tf(rw0.w);
        }
    }

#pragma unroll
    for (int mt = 0; mt < 2; ++mt) {
        const int row = bm * GBM + wm * 32 + mt * 16 + g;
#pragma unroll
        for (int nt = 0; nt < 4; ++nt) {
            const int col = bn * GBN + wn * 32 + nt * 8 + tg * 2;
            const float b0 = bias[col], b1 = bias[col + 1];
            float2 v0 = make_float2(acc[mt][nt][0] + b0, acc[mt][nt][1] + b1);
            float2 v1 = make_float2(acc[mt][nt][2] + b0, acc[mt][nt][3] + b1);
            *(float2*)(C + (size_t)row * N + col)       = v0;
            *(float2*)(C + (size_t)(row + 8) * N + col) = v1;
        }
    }
}

// ============================================================================
// Persistent recurrence kernel. 128 blocks x 256 threads.
// Block j: h-columns [8j,8j+8) -> 24 w_hh rows cached in smem as tf32.
// Warps = 2 m-groups x 4 k-quarters. Per step: stage h (double-buffered smem
// chunks), MMA, float4 partial reduction over 4 warps, fused gates on 128
// threads (one 2x2 output quad each) with gi prefetched one step ahead and
// h_prev held in registers. Grid barrier between steps.
// ============================================================================
#define RBLK 128
#define RTHR 256
#define RCOLS 8
#define WSTR 1028          // 24 x 1028 u32 tf32 w-slice (conflict-free)
#define HSTR 36            // 64 x 36 u32 per 32-k chunk (conflict-free)
#define HCHUNK_U32 (64 * HSTR)                 // 2304
#define WS_U32 (24 * WSTR)                     // 24672
#define RSM_U32 (WS_U32 + 2 * 4 * HCHUNK_U32)  // 43104 u32 = 172416 B

__device__ __forceinline__ void grid_bar(int t, unsigned nb) {
    __syncthreads();
    if (threadIdx.x == 0) {
        const unsigned tgt = (unsigned)(t / 2 + 1) * nb;
        unsigned* ctr = &g_cnt[t & 1];
        __threadfence();
        atomicAdd(ctr, 1u);
        unsigned v;
        do {
            asm volatile("ld.acquire.gpu.u32 %0, [%1];"
                         : "=r"(v) : "l"(ctr) : "memory");
        } while (v < tgt);
    }
    __syncthreads();
}

__device__ __forceinline__ float2 ldcs2(const float* p) {
    float2 v;
    asm volatile("ld.global.cs.v2.f32 {%0,%1}, [%2];"
                 : "=f"(v.x), "=f"(v.y) : "l"(p));
    return v;
}

__global__ void __launch_bounds__(RTHR, 1) gru_rec(
    const float* __restrict__ gi_base,  // [T][64][3072] (b_ih folded in)
    const float* __restrict__ h0,       // [64][1024]
    const float* __restrict__ w_hh,     // [3072][1024]
    const float* __restrict__ b_hh,     // [3072]
    float* __restrict__ hbuf0,
    float* __restrict__ hbuf1,
    float* __restrict__ y,              // [T][64][1024]
    float* __restrict__ hn)             // [64][1024]
{
    extern __shared__ uint32_t sm[];
    uint32_t* Ws  = sm;
    uint32_t* Hs  = sm + WS_U32;
    float4*  red4 = (float4*)(sm + WS_U32);  // 1792 f4 = 28KB, inside Hs buf0

    const int tid  = threadIdx.x;
    const int warp = tid >> 5, lane = tid & 31;
    const int g    = lane >> 2, tg = lane & 3;
    const int mg   = warp & 1;       // m-group: rows [mg*32, mg*32+32)
    const int kq   = warp >> 1;      // k-quarter
    const int j0   = blockIdx.x * RCOLS;
    const unsigned nb = gridDim.x;

    // ---- cache w_hh slice (24 rows x 1024) in smem as tf32, once ----
#pragma unroll 4
    for (int j = 0; j < 24; ++j) {
        const int u = tid + j * RTHR;
        const int r = u >> 8;
        const int q = u & 255;
        const int grow = (r >> 3) * HID + j0 + (r & 7);
        float4 v = *(const float4*)(w_hh + (size_t)grow * HID + q * 4);
        uint32_t* dst = Ws + r * WSTR + q * 4;
        dst[0] = f2tf(v.x); dst[1] = f2tf(v.y);
        dst[2] = f2tf(v.z); dst[3] = f2tf(v.w);
    }

    // ---- gate-thread setup (threads 0..127: one 2x2 output quad) ----
    // quad: rows {m0, m0+8}, cols {col, col+1}
    const int qc  = tid & 3;
    const int qa  = tid >> 2;
    const int qg  = qa & 7;
    const int qmt = (qa >> 3) & 1;
    const int qmg = (qa >> 4) & 1;
    const int m0  = qmg * 32 + qmt * 16 + qg;
    const int col = j0 + qc * 2;
    const int lane2 = qg * 4 + qc;

    float br0 = 0, br1 = 0, bz0 = 0, bz1 = 0, bn0 = 0, bn1 = 0;
    float2 gir[2][3];
    float4 hprev = make_float4(0, 0, 0, 0);
    if (tid < 128) {
        br0 = b_hh[col];           br1 = b_hh[col + 1];
        bz0 = b_hh[HID + col];     bz1 = b_hh[HID + col + 1];
        bn0 = b_hh[2 * HID + col]; bn1 = b_hh[2 * HID + col + 1];
        // prefetch gi for step 0
#pragma unroll
        for (int r = 0; r < 2; ++r) {
            const float* gim = gi_base + (size_t)(m0 + r * 8) * G3;
            gir[r][0] = ldcs2(gim + col);
            gir[r][1] = ldcs2(gim + HID + col);
            gir[r][2] = ldcs2(gim + 2 * HID + col);
        }
        float2 hp0 = *(const float2*)(h0 + m0 * HID + col);
        float2 hp1 = *(const float2*)(h0 + (m0 + 8) * HID + col);
        hprev = make_float4(hp0.x, hp0.y, hp1.x, hp1.y);
    }

    __syncthreads();

    for (int t = 0; t < TSTEPS; ++t) {
        const float* h_in = (t == 0) ? h0 : ((t & 1) ? hbuf0 : hbuf1);
        float* h_out = (t & 1) ? hbuf1 : hbuf0;

        float acc[2][3][4];
#pragma unroll
        for (int a = 0; a < 2; ++a)
#pragma unroll
            for (int b = 0; b < 3; ++b)
#pragma unroll
                for (int d = 0; d < 4; ++d) acc[a][b][d] = 0.0f;

        float4 rh[8];

        // prologue: load + stage chunk 0
#pragma unroll
        for (int j = 0; j < 8; ++j) {
            const int u = tid + j * RTHR;
            const int qu = u >> 9;
            const int v2 = u & 511;
            const int row = v2 >> 3, q8 = v2 & 7;
            rh[j] = __ldcg((const float4*)(h_in + row * HID + qu * 256 + q8 * 4));
        }
#pragma unroll
        for (int j = 0; j < 8; ++j) {
            const int u = tid + j * RTHR;
            const int qu = u >> 9;
            const int v2 = u & 511;
            const int row = v2 >> 3, q8 = v2 & 7;
            uint4 pv = make_uint4(f2tf(rh[j].x), f2tf(rh[j].y),
                                  f2tf(rh[j].z), f2tf(rh[j].w));
            *(uint4*)(Hs + qu * HCHUNK_U32 + row * HSTR + q8 * 4) = pv;
        }

        for (int c = 0; c < 8; ++c) {
            __syncthreads();
            if (c + 1 < 8) {
#pragma unroll
                for (int j = 0; j < 8; ++j) {
                    const int u = tid + j * RTHR;
                    const int qu = u >> 9;
                    const int v2 = u & 511;
                    const int row = v2 >> 3, q8 = v2 & 7;
                    const int gk = qu * 256 + (c + 1) * 32 + q8 * 4;
                    rh[j] = __ldcg((const float4*)(h_in + row * HID + gk));
                }
            }
            const uint32_t* Hq = Hs + ((c & 1) * 4 + kq) * HCHUNK_U32;
#pragma unroll
            for (int ks = 0; ks < 4; ++ks) {
                const int k0 = ks * 8;
                uint32_t a[2][4];
#pragma unroll
                for (int mt = 0; mt < 2; ++mt) {
                    const int rb = mg * 32 + mt * 16;
                    a[mt][0] = Hq[(rb + g    ) * HSTR + k0 + tg    ];
                    a[mt][1] = Hq[(rb + g + 8) * HSTR + k0 + tg    ];
                    a[mt][2] = Hq[(rb + g    ) * HSTR + k0 + tg + 4];
                    a[mt][3] = Hq[(rb + g + 8) * HSTR + k0 + tg + 4];
                }
                const int wk = kq * 256 + c * 32 + k0 + tg;
#pragma unroll
                for (int nt = 0; nt < 3; ++nt) {
                    const uint32_t b0 = Ws[(nt * 8 + g) * WSTR + wk    ];
                    const uint32_t b1 = Ws[(nt * 8 + g) * WSTR + wk + 4];
                    mma_tf32(acc[0][nt], a[0][0], a[0][1], a[0][2], a[0][3], b0, b1);
                    mma_tf32(acc[1][nt], a[1][0], a[1][1], a[1][2], a[1][3], b0, b1);
                }
            }
            if (c + 1 < 8) {
#pragma unroll
                for (int j = 0; j < 8; ++j) {
                    const int u = tid + j * RTHR;
                    const int qu = u >> 9;
                    const int v2 = u & 511;
                    const int row = v2 >> 3, q8 = v2 & 7;
                    uint4 pv = make_uint4(f2tf(rh[j].x), f2tf(rh[j].y),
                                          f2tf(rh[j].z), f2tf(rh[j].w));
                    *(uint4*)(Hs + (((c + 1) & 1) * 4 + qu) * HCHUNK_U32
                              + row * HSTR + q8 * 4) = pv;
                }
            }
        }

        // ---- store partials (red4 region = Hs buf0, disjoint from buf1
        //      which the last chunk's MMA reads -> no sync needed first) ----
        {
            const int base = ((kq * 2 + mg) * 32 + lane) * 7;
#pragma unroll
            for (int mt = 0; mt < 2; ++mt)
#pragma unroll
                for (int nt = 0; nt < 3; ++nt)
                    red4[base + mt * 3 + nt] =
                        make_float4(acc[mt][nt][0], acc[mt][nt][1],
                                    acc[mt][nt][2], acc[mt][nt][3]);
        }
        __syncthreads();

        if (tid < 128) {
            // gather partials (conflict-free: lane stride 7 f4 = 28 u32)
            float4 s[3];
#pragma unroll
            for (int nt = 0; nt < 3; ++nt)
                s[nt] = red4[((0 * 2 + qmg) * 32 + lane2) * 7 + qmt * 3 + nt];
#pragma unroll
            for (int q = 1; q < 4; ++q)
#pragma unroll
                for (int nt = 0; nt < 3; ++nt) {
                    float4 p = red4[((q * 2 + qmg) * 32 + lane2) * 7 + qmt * 3 + nt];
                    s[nt].x += p.x; s[nt].y += p.y; s[nt].z += p.z; s[nt].w += p.w;
                }

            // gates: rows {m0, m0+8}, cols {col, col+1}
            const float r00 = fsig(gir[0][0].x + s[0].x + br0);
            const float r01 = fsig(gir[0][0].y + s[0].y + br1);
            const float r10 = fsig(gir[1][0].x + s[0].z + br0);
            const float r11 = fsig(gir[1][0].y + s[0].w + br1);

            const float z00 = fsig(gir[0][1].x + s[1].x + bz0);
            const float z01 = fsig(gir[0][1].y + s[1].y + bz1);
            const float z10 = fsig(gir[1][1].x + s[1].z + bz0);
            const float z11 = fsig(gir[1][1].y + s[1].w + bz1);

            const float n00 = ftanh(gir[0][2].x + r00 * (s[2].x + bn0));
            const float n01 = ftanh(gir[0][2].y + r01 * (s[2].y + bn1));
            const float n10 = ftanh(gir[1][2].x + r10 * (s[2].z + bn0));
            const float n11 = ftanh(gir[1][2].y + r11 * (s[2].w + bn1));

            float4 hv;
            hv.x = (1.0f - z00) * n00 + z00 * hprev.x;
            hv.y = (1.0f - z01) * n01 + z01 * hprev.y;
            hv.z = (1.0f - z10) * n10 + z10 * hprev.z;
            hv.w = (1.0f - z11) * n11 + z11 * hprev.w;
            hprev = hv;

            float* y_t = y + (size_t)t * BATCH * HID;
            *(float2*)(h_out + m0 * HID + col)       = make_float2(hv.x, hv.y);
            *(float2*)(h_out + (m0 + 8) * HID + col) = make_float2(hv.z, hv.w);
            *(float2*)(y_t + m0 * HID + col)         = make_float2(hv.x, hv.y);
            *(float2*)(y_t + (m0 + 8) * HID + col)   = make_float2(hv.z, hv.w);
            if (t == TSTEPS - 1) {
                *(float2*)(hn + m0 * HID + col)       = make_float2(hv.x, hv.y);
                *(float2*)(hn + (m0 + 8) * HID + col) = make_float2(hv.z, hv.w);
            }

            // prefetch gi for step t+1 (independent of h -> hides DRAM latency
            // behind the grid barrier + next step's staging/MMA)
            if (t + 1 < TSTEPS) {
                const float* gi_n = gi_base + (size_t)(t + 1) * BATCH * G3;
#pragma unroll
                for (int r = 0; r < 2; ++r) {
                    const float* gim = gi_n + (size_t)(m0 + r * 8) * G3;
                    gir[r][0] = ldcs2(gim + col);
                    gir[r][1] = ldcs2(gim + HID + col);
                    gir[r][2] = ldcs2(gim + 2 * HID + col);
                }
            }
        }

        grid_bar(t, nb);
    }
}

__global__ void bar_reset() {
    g_cnt[0] = 0u;
    g_cnt[1] = 0u;
}

// ============================================================================
// Launcher: 6-node graph.
// ============================================================================
extern "C" void kernel_launch(void* const* d_in, const int* in_sizes, int n_in,
                              void* d_out, int out_size)
{
    const float* x      = (const float*)d_in[0];
    const float* hx     = (const float*)d_in[1];
    const float* w_ih_0 = (const float*)d_in[2];
    const float* w_hh_0 = (const float*)d_in[3];
    const float* b_ih_0 = (const float*)d_in[4];
    const float* b_hh_0 = (const float*)d_in[5];
    const float* w_ih_1 = (const float*)d_in[6];
    const float* w_hh_1 = (const float*)d_in[7];
    const float* b_ih_1 = (const float*)d_in[8];
    const float* b_hh_1 = (const float*)d_in[9];

    float* out = (float*)d_out;
    float* hn0 = out + (size_t)MROWS * HID;
    float* hn1 = hn0 + (size_t)BATCH * HID;

    float *gi, *y0, *ha, *hb;
    cudaGetSymbolAddress((void**)&gi, g_gi);
    cudaGetSymbolAddress((void**)&y0, g_y0);
    cudaGetSymbolAddress((void**)&ha, g_ha);
    cudaGetSymbolAddress((void**)&hb, g_hb);

    cudaFuncSetAttribute(gru_rec, cudaFuncAttributeMaxDynamicSharedMemorySize,
                         RSM_U32 * 4);

    dim3 ggrid(G3 / GBN, MROWS / GBM);  // (48, 256)

    // ---- layer 0 ----
    gemm_tn_bias<<<ggrid, 256>>>(x, w_ih_0, b_ih_0, gi, HID, G3);
    gru_rec<<<RBLK, RTHR, RSM_U32 * 4>>>(gi, hx, w_hh_0, b_hh_0,
                                         ha, hb, y0, hn0);
    bar_reset<<<1, 1>>>();

    // ---- layer 1 ----
    gemm_tn_bias<<<ggrid, 256>>>(y0, w_ih_1, b_ih_1, gi, HID, G3);
    gru_rec<<<RBLK, RTHR, RSM_U32 * 4>>>(gi, hx + (size_t)BATCH * HID,
                                         w_hh_1, b_hh_1,
                                         ha, hb, out, hn1);
    bar_reset<<<1, 1>>>();

    (void)in_sizes; (void)n_in; (void)out_size;
}

// round 10
// speedup vs baseline: 1.2260x; 1.0043x over previous
#include <cuda_runtime.h>
#include <cstdint>
#include <cstddef>

#define TSTEPS 512
#define BATCH  64
#define HID    1024
#define G3     3072
#define MROWS  (TSTEPS * BATCH)   // 32768

// ---- scratch (device globals; no runtime allocation allowed) ----
__device__ float g_gi[(size_t)MROWS * G3];   // 384 MB
__device__ float g_y0[(size_t)MROWS * HID];  // 128 MB
__device__ float g_ha[BATCH * HID];
__device__ float g_hb[BATCH * HID];
__device__ unsigned g_cnt[2];                // grid-barrier parity counters

// ---- helpers ----
__device__ __forceinline__ uint32_t f2tf(float f) {
    uint32_t u;
    asm("cvt.rna.tf32.f32 %0, %1;" : "=r"(u) : "f"(f));
    return u;
}

__device__ __forceinline__ void mma_tf32(float d[4],
    uint32_t a0, uint32_t a1, uint32_t a2, uint32_t a3,
    uint32_t b0, uint32_t b1)
{
    asm volatile(
        "mma.sync.aligned.m16n8k8.row.col.f32.tf32.tf32.f32 "
        "{%0,%1,%2,%3},{%4,%5,%6,%7},{%8,%9},{%0,%1,%2,%3};"
        : "+f"(d[0]), "+f"(d[1]), "+f"(d[2]), "+f"(d[3])
        : "r"(a0), "r"(a1), "r"(a2), "r"(a3), "r"(b0), "r"(b1));
}

__device__ __forceinline__ float frcp(float x) {
    float r; asm("rcp.approx.f32 %0, %1;" : "=f"(r) : "f"(x)); return r;
}
__device__ __forceinline__ float fex2(float x) {
    float r; asm("ex2.approx.f32 %0, %1;" : "=f"(r) : "f"(x)); return r;
}
__device__ __forceinline__ float fsig(float x) {
    return frcp(1.0f + fex2(-1.4426950408889634f * x));
}
__device__ __forceinline__ float ftanh(float x) {
    return 1.0f - 2.0f * frcp(1.0f + fex2(2.8853900817779268f * x));
}

// ============================================================================
// Big GEMM: C[M,N] = A[M,K] @ W[N,K]^T + bias[N]   (tf32 mma.sync, fp32 acc)
// Tiles: BM=128, BN=128, BK=16. 256 threads, 8 warps in 4x2; each warp does a
// 32x64 tile via 2x8 m16n8k8. Double-buffered smem, stride 20 (conflict-free).
// vs R4 (BN=64, 32x32/warp): halves A-fragment LDS bytes/MAC and halves
// staging traffic per MAC -> L1-wavefront bound relieved.
// ============================================================================
#define GBM 128
#define GBN 128
#define GBK 16
#define GSTR 20

__global__ __launch_bounds__(256) void gemm_tn_bias(
    const float* __restrict__ A,
    const float* __restrict__ W,
    const float* __restrict__ bias,
    float* __restrict__ C,
    int K, int N)
{
    __shared__ uint32_t As[2][GBM * GSTR];
    __shared__ uint32_t Bs[2][GBN * GSTR];

    const int t    = threadIdx.x;
    const int bm   = blockIdx.y, bn = blockIdx.x;
    const int warp = t >> 5, lane = t & 31;
    const int wm   = warp >> 1, wn = warp & 1;   // 4 x 2
    const int g    = lane >> 2, tg = lane & 3;

    const float* Ab = A + (size_t)bm * GBM * K;
    const float* Wb = W + (size_t)bn * GBN * K;

    const int lr = t >> 1;          // 0..127: staged row
    const int lq = (t & 1) * 8;     // 0 or 8: float offset within 16-k chunk

    float acc[2][8][4];
#pragma unroll
    for (int i = 0; i < 2; ++i)
#pragma unroll
        for (int j = 0; j < 8; ++j)
#pragma unroll
            for (int k = 0; k < 4; ++k) acc[i][j][k] = 0.0f;

    float4 ra0, ra1, rw0, rw1;

    // prologue: load k-chunk 0 and stage into buffer 0
    ra0 = *(const float4*)(Ab + (size_t)lr * K + lq);
    ra1 = *(const float4*)(Ab + (size_t)lr * K + lq + 4);
    rw0 = *(const float4*)(Wb + (size_t)lr * K + lq);
    rw1 = *(const float4*)(Wb + (size_t)lr * K + lq + 4);
    {
        uint32_t* as = As[0]; uint32_t* bs = Bs[0];
        as[lr * GSTR + lq + 0] = f2tf(ra0.x);
        as[lr * GSTR + lq + 1] = f2tf(ra0.y);
        as[lr * GSTR + lq + 2] = f2tf(ra0.z);
        as[lr * GSTR + lq + 3] = f2tf(ra0.w);
        as[lr * GSTR + lq + 4] = f2tf(ra1.x);
        as[lr * GSTR + lq + 5] = f2tf(ra1.y);
        as[lr * GSTR + lq + 6] = f2tf(ra1.z);
        as[lr * GSTR + lq + 7] = f2tf(ra1.w);
        bs[lr * GSTR + lq + 0] = f2tf(rw0.x);
        bs[lr * GSTR + lq + 1] = f2tf(rw0.y);
        bs[lr * GSTR + lq + 2] = f2tf(rw0.z);
        bs[lr * GSTR + lq + 3] = f2tf(rw0.w);
        bs[lr * GSTR + lq + 4] = f2tf(rw1.x);
        bs[lr * GSTR + lq + 5] = f2tf(rw1.y);
        bs[lr * GSTR + lq + 6] = f2tf(rw1.z);
        bs[lr * GSTR + lq + 7] = f2tf(rw1.w);
    }

    const int NCH = K / GBK;
    for (int c = 0; c < NCH; ++c) {
        __syncthreads();
        const int b = c & 1;
        if (c + 1 < NCH) {
            const int kg = (c + 1) * GBK;
            ra0 = *(const float4*)(Ab + (size_t)lr * K + kg + lq);
            ra1 = *(const float4*)(Ab + (size_t)lr * K + kg + lq + 4);
            rw0 = *(const float4*)(Wb + (size_t)lr * K + kg + lq);
            rw1 = *(const float4*)(Wb + (size_t)lr * K + kg + lq + 4);
        }
#pragma unroll
        for (int ks = 0; ks < 2; ++ks) {
            const int k0 = ks * 8;
            uint32_t af[2][4], bf[8][2];
#pragma unroll
            for (int mt = 0; mt < 2; ++mt) {
                const int rb = wm * 32 + mt * 16;
                af[mt][0] = As[b][(rb + g    ) * GSTR + k0 + tg    ];
                af[mt][1] = As[b][(rb + g + 8) * GSTR + k0 + tg    ];
                af[mt][2] = As[b][(rb + g    ) * GSTR + k0 + tg + 4];
                af[mt][3] = As[b][(rb + g + 8) * GSTR + k0 + tg + 4];
            }
#pragma unroll
            for (int nt = 0; nt < 8; ++nt) {
                const int nb = wn * 64 + nt * 8;
                bf[nt][0] = Bs[b][(nb + g) * GSTR + k0 + tg    ];
                bf[nt][1] = Bs[b][(nb + g) * GSTR + k0 + tg + 4];
            }
#pragma unroll
            for (int mt = 0; mt < 2; ++mt)
#pragma unroll
                for (int nt = 0; nt < 8; ++nt)
                    mma_tf32(acc[mt][nt],
                             af[mt][0], af[mt][1], af[mt][2], af[mt][3],
                             bf[nt][0], bf[nt][1]);
        }
        if (c + 1 < NCH) {
            const int nb2 = (c + 1) & 1;
            uint32_t* as = As[nb2]; uint32_t* bs = Bs[nb2];
            as[lr * GSTR + lq + 0] = f2tf(ra0.x);
            as[lr * GSTR + lq + 1] = f2tf(ra0.y);
            as[lr * GSTR + lq + 2] = f2tf(ra0.z);
            as[lr * GSTR + lq + 3] = f2tf(ra0.w);
            as[lr * GSTR + lq + 4] = f2tf(ra1.x);
            as[lr * GSTR + lq + 5] = f2tf(ra1.y);
            as[lr * GSTR + lq + 6] = f2tf(ra1.z);
            as[lr * GSTR + lq + 7] = f2tf(ra1.w);
            bs[lr * GSTR + lq + 0] = f2tf(rw0.x);
            bs[lr * GSTR + lq + 1] = f2tf(rw0.y);
            bs[lr * GSTR + lq + 2] = f2tf(rw0.z);
            bs[lr * GSTR + lq + 3] = f2tf(rw0.w);
            bs[lr * GSTR + lq + 4] = f2tf(rw1.x);
            bs[lr * GSTR + lq + 5] = f2tf(rw1.y);
            bs[lr * GSTR + lq + 6] = f2tf(rw1.z);
            bs[lr * GSTR + lq + 7] = f2tf(rw1.w);
        }
    }

    // epilogue: + bias, fp32 out
#pragma unroll
    for (int mt = 0; mt < 2; ++mt) {
        const int row = bm * GBM + wm * 32 + mt * 16 + g;
#pragma unroll
        for (int nt = 0; nt < 8; ++nt) {
            const int col = bn * GBN + wn * 64 + nt * 8 + tg * 2;
            const float b0 = bias[col], b1 = bias[col + 1];
            float2 v0 = make_float2(acc[mt][nt][0] + b0, acc[mt][nt][1] + b1);
            float2 v1 = make_float2(acc[mt][nt][2] + b0, acc[mt][nt][3] + b1);
            *(float2*)(C + (size_t)row * N + col)       = v0;
            *(float2*)(C + (size_t)(row + 8) * N + col) = v1;
        }
    }
}

// ============================================================================
// Persistent recurrence kernel (unchanged from R4 — proven).
// ============================================================================
#define RBLK 128
#define RTHR 256
#define RCOLS 8
#define WSTR 1028
#define HSTR 36
#define HCHUNK_U32 (64 * HSTR)
#define WS_U32 (24 * WSTR)
#define RSM_U32 (WS_U32 + 2 * 4 * HCHUNK_U32)

__device__ __forceinline__ void grid_bar(int t, unsigned nb) {
    __syncthreads();
    if (threadIdx.x == 0) {
        const unsigned tgt = (unsigned)(t / 2 + 1) * nb;
        unsigned* ctr = &g_cnt[t & 1];
        __threadfence();
        atomicAdd(ctr, 1u);
        unsigned v;
        do {
            asm volatile("ld.acquire.gpu.u32 %0, [%1];"
                         : "=r"(v) : "l"(ctr) : "memory");
        } while (v < tgt);
    }
    __syncthreads();
}

__device__ __forceinline__ float2 ldcs2(const float* p) {
    float2 v;
    asm volatile("ld.global.cs.v2.f32 {%0,%1}, [%2];"
                 : "=f"(v.x), "=f"(v.y) : "l"(p));
    return v;
}

__global__ void __launch_bounds__(RTHR, 1) gru_rec(
    const float* __restrict__ gi_base,
    const float* __restrict__ h0,
    const float* __restrict__ w_hh,
    const float* __restrict__ b_hh,
    float* __restrict__ hbuf0,
    float* __restrict__ hbuf1,
    float* __restrict__ y,
    float* __restrict__ hn)
{
    extern __shared__ uint32_t sm[];
    uint32_t* Ws  = sm;
    uint32_t* Hs  = sm + WS_U32;
    float4*  red4 = (float4*)(sm + WS_U32);

    const int tid  = threadIdx.x;
    const int warp = tid >> 5, lane = tid & 31;
    const int g    = lane >> 2, tg = lane & 3;
    const int mg   = warp & 1;
    const int kq   = warp >> 1;
    const int j0   = blockIdx.x * RCOLS;
    const unsigned nb = gridDim.x;

#pragma unroll 4
    for (int j = 0; j < 24; ++j) {
        const int u = tid + j * RTHR;
        const int r = u >> 8;
        const int q = u & 255;
        const int grow = (r >> 3) * HID + j0 + (r & 7);
        float4 v = *(const float4*)(w_hh + (size_t)grow * HID + q * 4);
        uint32_t* dst = Ws + r * WSTR + q * 4;
        dst[0] = f2tf(v.x); dst[1] = f2tf(v.y);
        dst[2] = f2tf(v.z); dst[3] = f2tf(v.w);
    }

    const int qc  = tid & 3;
    const int qa  = tid >> 2;
    const int qg  = qa & 7;
    const int qmt = (qa >> 3) & 1;
    const int qmg = (qa >> 4) & 1;
    const int m0  = qmg * 32 + qmt * 16 + qg;
    const int col = j0 + qc * 2;
    const int lane2 = qg * 4 + qc;

    float br0 = 0, br1 = 0, bz0 = 0, bz1 = 0, bn0 = 0, bn1 = 0;
    float2 gir[2][3];
    float4 hprev = make_float4(0, 0, 0, 0);
    if (tid < 128) {
        br0 = b_hh[col];           br1 = b_hh[col + 1];
        bz0 = b_hh[HID + col];     bz1 = b_hh[HID + col + 1];
        bn0 = b_hh[2 * HID + col]; bn1 = b_hh[2 * HID + col + 1];
#pragma unroll
        for (int r = 0; r < 2; ++r) {
            const float* gim = gi_base + (size_t)(m0 + r * 8) * G3;
            gir[r][0] = ldcs2(gim + col);
            gir[r][1] = ldcs2(gim + HID + col);
            gir[r][2] = ldcs2(gim + 2 * HID + col);
        }
        float2 hp0 = *(const float2*)(h0 + m0 * HID + col);
        float2 hp1 = *(const float2*)(h0 + (m0 + 8) * HID + col);
        hprev = make_float4(hp0.x, hp0.y, hp1.x, hp1.y);
    }

    __syncthreads();

    for (int t = 0; t < TSTEPS; ++t) {
        const float* h_in = (t == 0) ? h0 : ((t & 1) ? hbuf0 : hbuf1);
        float* h_out = (t & 1) ? hbuf1 : hbuf0;

        float acc[2][3][4];
#pragma unroll
        for (int a = 0; a < 2; ++a)
#pragma unroll
            for (int b = 0; b < 3; ++b)
#pragma unroll
                for (int d = 0; d < 4; ++d) acc[a][b][d] = 0.0f;

        float4 rh[8];

#pragma unroll
        for (int j = 0; j < 8; ++j) {
            const int u = tid + j * RTHR;
            const int qu = u >> 9;
            const int v2 = u & 511;
            const int row = v2 >> 3, q8 = v2 & 7;
            rh[j] = __ldcg((const float4*)(h_in + row * HID + qu * 256 + q8 * 4));
        }
#pragma unroll
        for (int j = 0; j < 8; ++j) {
            const int u = tid + j * RTHR;
            const int qu = u >> 9;
            const int v2 = u & 511;
            const int row = v2 >> 3, q8 = v2 & 7;
            uint4 pv = make_uint4(f2tf(rh[j].x), f2tf(rh[j].y),
                                  f2tf(rh[j].z), f2tf(rh[j].w));
            *(uint4*)(Hs + qu * HCHUNK_U32 + row * HSTR + q8 * 4) = pv;
        }

        for (int c = 0; c < 8; ++c) {
            __syncthreads();
            if (c + 1 < 8) {
#pragma unroll
                for (int j = 0; j < 8; ++j) {
                    const int u = tid + j * RTHR;
                    const int qu = u >> 9;
                    const int v2 = u & 511;
                    const int row = v2 >> 3, q8 = v2 & 7;
                    const int gk = qu * 256 + (c + 1) * 32 + q8 * 4;
                    rh[j] = __ldcg((const float4*)(h_in + row * HID + gk));
                }
            }
            const uint32_t* Hq = Hs + ((c & 1) * 4 + kq) * HCHUNK_U32;
#pragma unroll
            for (int ks = 0; ks < 4; ++ks) {
                const int k0 = ks * 8;
                uint32_t a[2][4];
#pragma unroll
                for (int mt = 0; mt < 2; ++mt) {
                    const int rb = mg * 32 + mt * 16;
                    a[mt][0] = Hq[(rb + g    ) * HSTR + k0 + tg    ];
                    a[mt][1] = Hq[(rb + g + 8) * HSTR + k0 + tg    ];
                    a[mt][2] = Hq[(rb + g    ) * HSTR + k0 + tg + 4];
                    a[mt][3] = Hq[(rb + g + 8) * HSTR + k0 + tg + 4];
                }
                const int wk = kq * 256 + c * 32 + k0 + tg;
#pragma unroll
                for (int nt = 0; nt < 3; ++nt) {
                    const uint32_t b0 = Ws[(nt * 8 + g) * WSTR + wk    ];
                    const uint32_t b1 = Ws[(nt * 8 + g) * WSTR + wk + 4];
                    mma_tf32(acc[0][nt], a[0][0], a[0][1], a[0][2], a[0][3], b0, b1);
                    mma_tf32(acc[1][nt], a[1][0], a[1][1], a[1][2], a[1][3], b0, b1);
                }
            }
            if (c + 1 < 8) {
#pragma unroll
                for (int j = 0; j < 8; ++j) {
                    const int u = tid + j * RTHR;
                    const int qu = u >> 9;
                    const int v2 = u & 511;
                    const int row = v2 >> 3, q8 = v2 & 7;
                    uint4 pv = make_uint4(f2tf(rh[j].x), f2tf(rh[j].y),
                                          f2tf(rh[j].z), f2tf(rh[j].w));
                    *(uint4*)(Hs + (((c + 1) & 1) * 4 + qu) * HCHUNK_U32
                              + row * HSTR + q8 * 4) = pv;
                }
            }
        }

        {
            const int base = ((kq * 2 + mg) * 32 + lane) * 7;
#pragma unroll
            for (int mt = 0; mt < 2; ++mt)
#pragma unroll
                for (int nt = 0; nt < 3; ++nt)
                    red4[base + mt * 3 + nt] =
                        make_float4(acc[mt][nt][0], acc[mt][nt][1],
                                    acc[mt][nt][2], acc[mt][nt][3]);
        }
        __syncthreads();

        if (tid < 128) {
            float4 s[3];
#pragma unroll
            for (int nt = 0; nt < 3; ++nt)
                s[nt] = red4[((0 * 2 + qmg) * 32 + lane2) * 7 + qmt * 3 + nt];
#pragma unroll
            for (int q = 1; q < 4; ++q)
#pragma unroll
                for (int nt = 0; nt < 3; ++nt) {
                    float4 p = red4[((q * 2 + qmg) * 32 + lane2) * 7 + qmt * 3 + nt];
                    s[nt].x += p.x; s[nt].y += p.y; s[nt].z += p.z; s[nt].w += p.w;
                }

            const float r00 = fsig(gir[0][0].x + s[0].x + br0);
            const float r01 = fsig(gir[0][0].y + s[0].y + br1);
            const float r10 = fsig(gir[1][0].x + s[0].z + br0);
            const float r11 = fsig(gir[1][0].y + s[0].w + br1);

            const float z00 = fsig(gir[0][1].x + s[1].x + bz0);
            const float z01 = fsig(gir[0][1].y + s[1].y + bz1);
            const float z10 = fsig(gir[1][1].x + s[1].z + bz0);
            const float z11 = fsig(gir[1][1].y + s[1].w + bz1);

            const float n00 = ftanh(gir[0][2].x + r00 * (s[2].x + bn0));
            const float n01 = ftanh(gir[0][2].y + r01 * (s[2].y + bn1));
            const float n10 = ftanh(gir[1][2].x + r10 * (s[2].z + bn0));
            const float n11 = ftanh(gir[1][2].y + r11 * (s[2].w + bn1));

            float4 hv;
            hv.x = (1.0f - z00) * n00 + z00 * hprev.x;
            hv.y = (1.0f - z01) * n01 + z01 * hprev.y;
            hv.z = (1.0f - z10) * n10 + z10 * hprev.z;
            hv.w = (1.0f - z11) * n11 + z11 * hprev.w;
            hprev = hv;

            float* y_t = y + (size_t)t * BATCH * HID;
            *(float2*)(h_out + m0 * HID + col)       = make_float2(hv.x, hv.y);
            *(float2*)(h_out + (m0 + 8) * HID + col) = make_float2(hv.z, hv.w);
            *(float2*)(y_t + m0 * HID + col)         = make_float2(hv.x, hv.y);
            *(float2*)(y_t + (m0 + 8) * HID + col)   = make_float2(hv.z, hv.w);
            if (t == TSTEPS - 1) {
                *(float2*)(hn + m0 * HID + col)       = make_float2(hv.x, hv.y);
                *(float2*)(hn + (m0 + 8) * HID + col) = make_float2(hv.z, hv.w);
            }

            if (t + 1 < TSTEPS) {
                const float* gi_n = gi_base + (size_t)(t + 1) * BATCH * G3;
#pragma unroll
                for (int r = 0; r < 2; ++r) {
                    const float* gim = gi_n + (size_t)(m0 + r * 8) * G3;
                    gir[r][0] = ldcs2(gim + col);
                    gir[r][1] = ldcs2(gim + HID + col);
                    gir[r][2] = ldcs2(gim + 2 * HID + col);
                }
            }
        }

        grid_bar(t, nb);
    }
}

__global__ void bar_reset() {
    g_cnt[0] = 0u;
    g_cnt[1] = 0u;
}

// ============================================================================
// Launcher: 6-node graph.
// ============================================================================
extern "C" void kernel_launch(void* const* d_in, const int* in_sizes, int n_in,
                              void* d_out, int out_size)
{
    const float* x      = (const float*)d_in[0];
    const float* hx     = (const float*)d_in[1];
    const float* w_ih_0 = (const float*)d_in[2];
    const float* w_hh_0 = (const float*)d_in[3];
    const float* b_ih_0 = (const float*)d_in[4];
    const float* b_hh_0 = (const float*)d_in[5];
    const float* w_ih_1 = (const float*)d_in[6];
    const float* w_hh_1 = (const float*)d_in[7];
    const float* b_ih_1 = (const float*)d_in[8];
    const float* b_hh_1 = (const float*)d_in[9];

    float* out = (float*)d_out;
    float* hn0 = out + (size_t)MROWS * HID;
    float* hn1 = hn0 + (size_t)BATCH * HID;

    float *gi, *y0, *ha, *hb;
    cudaGetSymbolAddress((void**)&gi, g_gi);
    cudaGetSymbolAddress((void**)&y0, g_y0);
    cudaGetSymbolAddress((void**)&ha, g_ha);
    cudaGetSymbolAddress((void**)&hb, g_hb);

    cudaFuncSetAttribute(gru_rec, cudaFuncAttributeMaxDynamicSharedMemorySize,
                         RSM_U32 * 4);

    dim3 ggrid(G3 / GBN, MROWS / GBM);  // (24, 256)

    // ---- layer 0 ----
    gemm_tn_bias<<<ggrid, 256>>>(x, w_ih_0, b_ih_0, gi, HID, G3);
    gru_rec<<<RBLK, RTHR, RSM_U32 * 4>>>(gi, hx, w_hh_0, b_hh_0,
                                         ha, hb, y0, hn0);
    bar_reset<<<1, 1>>>();

    // ---- layer 1 ----
    gemm_tn_bias<<<ggrid, 256>>>(y0, w_ih_1, b_ih_1, gi, HID, G3);
    gru_rec<<<RBLK, RTHR, RSM_U32 * 4>>>(gi, hx + (size_t)BATCH * HID,
                                         w_hh_1, b_hh_1,
                                         ha, hb, out, hn1);
    bar_reset<<<1, 1>>>();

    (void)in_sizes; (void)n_in; (void)out_size;
}

// round 14
// speedup vs baseline: 1.3785x; 1.1244x over previous
#include <cuda_runtime.h>
#include <cstdint>
#include <cstddef>

#define TSTEPS 512
#define BATCH  64
#define HID    1024
#define G3     3072
#define MROWS  (TSTEPS * BATCH)   // 32768

// ---- scratch (device globals; no runtime allocation allowed) ----
__device__ float g_gi[(size_t)MROWS * G3];   // 384 MB
__device__ float g_y0[(size_t)MROWS * HID];  // 128 MB
__device__ float g_ha[BATCH * HID];
__device__ float g_hb[BATCH * HID];
__device__ unsigned g_cnt[2];                // grid-barrier parity counters

// ---- helpers ----
__device__ __forceinline__ uint32_t f2tf(float f) {
    uint32_t u;
    asm("cvt.rna.tf32.f32 %0, %1;" : "=r"(u) : "f"(f));
    return u;
}

__device__ __forceinline__ void mma_tf32(float d[4],
    uint32_t a0, uint32_t a1, uint32_t a2, uint32_t a3,
    uint32_t b0, uint32_t b1)
{
    asm volatile(
        "mma.sync.aligned.m16n8k8.row.col.f32.tf32.tf32.f32 "
        "{%0,%1,%2,%3},{%4,%5,%6,%7},{%8,%9},{%0,%1,%2,%3};"
        : "+f"(d[0]), "+f"(d[1]), "+f"(d[2]), "+f"(d[3])
        : "r"(a0), "r"(a1), "r"(a2), "r"(a3), "r"(b0), "r"(b1));
}

__device__ __forceinline__ float frcp(float x) {
    float r; asm("rcp.approx.f32 %0, %1;" : "=f"(r) : "f"(x)); return r;
}
__device__ __forceinline__ float fex2(float x) {
    float r; asm("ex2.approx.f32 %0, %1;" : "=f"(r) : "f"(x)); return r;
}
__device__ __forceinline__ float fsig(float x) {
    return frcp(1.0f + fex2(-1.4426950408889634f * x));
}
__device__ __forceinline__ float ftanh(float x) {
    return 1.0f - 2.0f * frcp(1.0f + fex2(2.8853900817779268f * x));
}

// ============================================================================
// Big GEMM (unchanged from R10): C = A @ W^T + bias, tf32 mma.sync.
// BM=128, BN=128, BK=16, 8 warps x (32x64).
// ============================================================================
#define GBM 128
#define GBN 128
#define GBK 16
#define GSTR 20

__global__ __launch_bounds__(256) void gemm_tn_bias(
    const float* __restrict__ A,
    const float* __restrict__ W,
    const float* __restrict__ bias,
    float* __restrict__ C,
    int K, int N)
{
    __shared__ uint32_t As[2][GBM * GSTR];
    __shared__ uint32_t Bs[2][GBN * GSTR];

    const int t    = threadIdx.x;
    const int bm   = blockIdx.y, bn = blockIdx.x;
    const int warp = t >> 5, lane = t & 31;
    const int wm   = warp >> 1, wn = warp & 1;
    const int g    = lane >> 2, tg = lane & 3;

    const float* Ab = A + (size_t)bm * GBM * K;
    const float* Wb = W + (size_t)bn * GBN * K;

    const int lr = t >> 1;
    const int lq = (t & 1) * 8;

    float acc[2][8][4];
#pragma unroll
    for (int i = 0; i < 2; ++i)
#pragma unroll
        for (int j = 0; j < 8; ++j)
#pragma unroll
            for (int k = 0; k < 4; ++k) acc[i][j][k] = 0.0f;

    float4 ra0, ra1, rw0, rw1;

    ra0 = *(const float4*)(Ab + (size_t)lr * K + lq);
    ra1 = *(const float4*)(Ab + (size_t)lr * K + lq + 4);
    rw0 = *(const float4*)(Wb + (size_t)lr * K + lq);
    rw1 = *(const float4*)(Wb + (size_t)lr * K + lq + 4);
    {
        uint32_t* as = As[0]; uint32_t* bs = Bs[0];
        as[lr * GSTR + lq + 0] = f2tf(ra0.x);
        as[lr * GSTR + lq + 1] = f2tf(ra0.y);
        as[lr * GSTR + lq + 2] = f2tf(ra0.z);
        as[lr * GSTR + lq + 3] = f2tf(ra0.w);
        as[lr * GSTR + lq + 4] = f2tf(ra1.x);
        as[lr * GSTR + lq + 5] = f2tf(ra1.y);
        as[lr * GSTR + lq + 6] = f2tf(ra1.z);
        as[lr * GSTR + lq + 7] = f2tf(ra1.w);
        bs[lr * GSTR + lq + 0] = f2tf(rw0.x);
        bs[lr * GSTR + lq + 1] = f2tf(rw0.y);
        bs[lr * GSTR + lq + 2] = f2tf(rw0.z);
        bs[lr * GSTR + lq + 3] = f2tf(rw0.w);
        bs[lr * GSTR + lq + 4] = f2tf(rw1.x);
        bs[lr * GSTR + lq + 5] = f2tf(rw1.y);
        bs[lr * GSTR + lq + 6] = f2tf(rw1.z);
        bs[lr * GSTR + lq + 7] = f2tf(rw1.w);
    }

    const int NCH = K / GBK;
    for (int c = 0; c < NCH; ++c) {
        __syncthreads();
        const int b = c & 1;
        if (c + 1 < NCH) {
            const int kg = (c + 1) * GBK;
            ra0 = *(const float4*)(Ab + (size_t)lr * K + kg + lq);
            ra1 = *(const float4*)(Ab + (size_t)lr * K + kg + lq + 4);
            rw0 = *(const float4*)(Wb + (size_t)lr * K + kg + lq);
            rw1 = *(const float4*)(Wb + (size_t)lr * K + kg + lq + 4);
        }
#pragma unroll
        for (int ks = 0; ks < 2; ++ks) {
            const int k0 = ks * 8;
            uint32_t af[2][4], bf[8][2];
#pragma unroll
            for (int mt = 0; mt < 2; ++mt) {
                const int rb = wm * 32 + mt * 16;
                af[mt][0] = As[b][(rb + g    ) * GSTR + k0 + tg    ];
                af[mt][1] = As[b][(rb + g + 8) * GSTR + k0 + tg    ];
                af[mt][2] = As[b][(rb + g    ) * GSTR + k0 + tg + 4];
                af[mt][3] = As[b][(rb + g + 8) * GSTR + k0 + tg + 4];
            }
#pragma unroll
            for (int nt = 0; nt < 8; ++nt) {
                const int nb = wn * 64 + nt * 8;
                bf[nt][0] = Bs[b][(nb + g) * GSTR + k0 + tg    ];
                bf[nt][1] = Bs[b][(nb + g) * GSTR + k0 + tg + 4];
            }
#pragma unroll
            for (int mt = 0; mt < 2; ++mt)
#pragma unroll
                for (int nt = 0; nt < 8; ++nt)
                    mma_tf32(acc[mt][nt],
                             af[mt][0], af[mt][1], af[mt][2], af[mt][3],
                             bf[nt][0], bf[nt][1]);
        }
        if (c + 1 < NCH) {
            const int nb2 = (c + 1) & 1;
            uint32_t* as = As[nb2]; uint32_t* bs = Bs[nb2];
            as[lr * GSTR + lq + 0] = f2tf(ra0.x);
            as[lr * GSTR + lq + 1] = f2tf(ra0.y);
            as[lr * GSTR + lq + 2] = f2tf(ra0.z);
            as[lr * GSTR + lq + 3] = f2tf(ra0.w);
            as[lr * GSTR + lq + 4] = f2tf(ra1.x);
            as[lr * GSTR + lq + 5] = f2tf(ra1.y);
            as[lr * GSTR + lq + 6] = f2tf(ra1.z);
            as[lr * GSTR + lq + 7] = f2tf(ra1.w);
            bs[lr * GSTR + lq + 0] = f2tf(rw0.x);
            bs[lr * GSTR + lq + 1] = f2tf(rw0.y);
            bs[lr * GSTR + lq + 2] = f2tf(rw0.z);
            bs[lr * GSTR + lq + 3] = f2tf(rw0.w);
            bs[lr * GSTR + lq + 4] = f2tf(rw1.x);
            bs[lr * GSTR + lq + 5] = f2tf(rw1.y);
            bs[lr * GSTR + lq + 6] = f2tf(rw1.z);
            bs[lr * GSTR + lq + 7] = f2tf(rw1.w);
        }
    }

#pragma unroll
    for (int mt = 0; mt < 2; ++mt) {
        const int row = bm * GBM + wm * 32 + mt * 16 + g;
#pragma unroll
        for (int nt = 0; nt < 8; ++nt) {
            const int col = bn * GBN + wn * 64 + nt * 8 + tg * 2;
            const float b0 = bias[col], b1 = bias[col + 1];
            float2 v0 = make_float2(acc[mt][nt][0] + b0, acc[mt][nt][1] + b1);
            float2 v1 = make_float2(acc[mt][nt][2] + b0, acc[mt][nt][3] + b1);
            *(float2*)(C + (size_t)row * N + col)       = v0;
            *(float2*)(C + (size_t)(row + 8) * N + col) = v1;
        }
    }
}

// ============================================================================
// Persistent recurrence kernel, warp-autonomous mainloop (R11).
// 128 blocks x 256 threads. Block j: cols [8j,8j+8), 24 w rows in smem (tf32).
// Warp (mg,kq) owns h rows [mg*32,+32) x k [kq*256,+256): private double-
// buffered staging (32x32k chunks), 2-deep LDG pipeline, __syncwarp only.
// One __syncthreads before the 256-thread reduction+gate phase.
// ============================================================================
#define RBLK 128
#define RTHR 256
#define RCOLS 8
#define WSTR 1028
#define HSTR 36
#define WBUF_U32 (32 * HSTR)                  // 1152: one 32-row x 32-k chunk
#define WS_U32 (24 * WSTR)                    // 24672
#define RED_OFF (WS_U32 + 8 * 2 * WBUF_U32)   // after 8 warp double-buffers
#define RED_U32 (8 * 32 * 7 * 4)              // 7168 u32 (1792 float4)
#define RSM_U32 (RED_OFF + RED_U32)           // 50272 u32 = 201088 B

__device__ __forceinline__ void grid_bar(int t, unsigned nb) {
    __syncthreads();
    if (threadIdx.x == 0) {
        const unsigned tgt = (unsigned)(t / 2 + 1) * nb;
        unsigned* ctr = &g_cnt[t & 1];
        __threadfence();
        atomicAdd(ctr, 1u);
        unsigned v;
        do {
            asm volatile("ld.acquire.gpu.u32 %0, [%1];"
                         : "=r"(v) : "l"(ctr) : "memory");
        } while (v < tgt);
    }
    __syncthreads();
}

__device__ __forceinline__ float2 ldcs2(const float* p) {
    float2 v;
    asm volatile("ld.global.cs.v2.f32 {%0,%1}, [%2];"
                 : "=f"(v.x), "=f"(v.y) : "l"(p));
    return v;
}

__global__ void __launch_bounds__(RTHR, 1) gru_rec(
    const float* __restrict__ gi_base,
    const float* __restrict__ h0,
    const float* __restrict__ w_hh,
    const float* __restrict__ b_hh,
    float* __restrict__ hbuf0,
    float* __restrict__ hbuf1,
    float* __restrict__ y,
    float* __restrict__ hn)
{
    extern __shared__ uint32_t sm[];
    uint32_t* Ws   = sm;
    float4*   red4 = (float4*)(sm + RED_OFF);
    float2*   red2 = (float2*)red4;

    const int tid  = threadIdx.x;
    const int warp = tid >> 5, lane = tid & 31;
    const int g    = lane >> 2, tg = lane & 3;
    const int mg   = warp & 1;
    const int kq   = warp >> 1;
    const int j0   = blockIdx.x * RCOLS;
    const unsigned nb = gridDim.x;

    uint32_t* Hw = sm + WS_U32 + warp * (2 * WBUF_U32);

    // ---- cache w_hh slice (24 rows x 1024) in smem as tf32, once ----
#pragma unroll 4
    for (int j = 0; j < 24; ++j) {
        const int u = tid + j * RTHR;
        const int r = u >> 8;
        const int q = u & 255;
        const int grow = (r >> 3) * HID + j0 + (r & 7);
        float4 v = *(const float4*)(w_hh + (size_t)grow * HID + q * 4);
        uint32_t* dst = Ws + r * WSTR + q * 4;
        dst[0] = f2tf(v.x); dst[1] = f2tf(v.y);
        dst[2] = f2tf(v.z); dst[3] = f2tf(v.w);
    }

    // ---- gate-thread mapping: all 256 threads, one float2 output each ----
    // thread -> row m = tid>>2 (0..63), col pair qc = tid&3
    const int qc   = tid & 3;
    const int m    = tid >> 2;
    const int col  = j0 + qc * 2;
    const int mg_o = m >> 5;
    const int mt_o = (m >> 4) & 1;
    const int hi   = (m >> 3) & 1;        // uniform within a warp
    const int g_o  = m & 7;
    const int lane2 = g_o * 4 + qc;

    const float2 bhr = *(const float2*)(b_hh + col);
    const float2 bhz = *(const float2*)(b_hh + HID + col);
    const float2 bhn = *(const float2*)(b_hh + 2 * HID + col);

    float2 gi_r = ldcs2(gi_base + (size_t)m * G3 + col);
    float2 gi_z = ldcs2(gi_base + (size_t)m * G3 + HID + col);
    float2 gi_n = ldcs2(gi_base + (size_t)m * G3 + 2 * HID + col);
    float2 hprev = *(const float2*)(h0 + m * HID + col);

    // per-warp staging lane mapping: item = lane + 32*i -> row lrow+4i, 16B col lq8
    const int lrow = lane >> 3;
    const int lq8  = lane & 7;

    __syncthreads();

    for (int t = 0; t < TSTEPS; ++t) {
        const float* h_in = (t == 0) ? h0 : ((t & 1) ? hbuf0 : hbuf1);
        float* h_out = (t & 1) ? hbuf1 : hbuf0;

        float acc[2][3][4];
#pragma unroll
        for (int a = 0; a < 2; ++a)
#pragma unroll
            for (int b = 0; b < 3; ++b)
#pragma unroll
                for (int d = 0; d < 4; ++d) acc[a][b][d] = 0.0f;

        // warp's h region base: rows mg*32.., k quarter kq*256..
        const float* hq = h_in + (size_t)(mg * 32 + lrow) * HID + kq * 256 + lq8 * 4;

        float4 ra[8], rb[8];

        // ---- prologue: chunk0 -> buf0; chunk1 -> ra ----
#pragma unroll
        for (int i = 0; i < 8; ++i)
            ra[i] = __ldcg((const float4*)(hq + (size_t)i * 4 * HID));
#pragma unroll
        for (int i = 0; i < 8; ++i) {
            uint4 pv = make_uint4(f2tf(ra[i].x), f2tf(ra[i].y),
                                  f2tf(ra[i].z), f2tf(ra[i].w));
            *(uint4*)(Hw + (lrow + i * 4) * HSTR + lq8 * 4) = pv;
        }
#pragma unroll
        for (int i = 0; i < 8; ++i)
            ra[i] = __ldcg((const float4*)(hq + (size_t)i * 4 * HID + 32));
        __syncwarp();

        // ---- warp-autonomous 2-deep pipeline over 8 chunks ----
#pragma unroll
        for (int c = 0; c < 8; ++c) {
            if (c + 2 < 8) {
                const float* src = hq + (c + 2) * 32;
                if (c & 1) {
#pragma unroll
                    for (int i = 0; i < 8; ++i)
                        ra[i] = __ldcg((const float4*)(src + (size_t)i * 4 * HID));
                } else {
#pragma unroll
                    for (int i = 0; i < 8; ++i)
                        rb[i] = __ldcg((const float4*)(src + (size_t)i * 4 * HID));
                }
            }
            const uint32_t* Hc = Hw + (c & 1) * WBUF_U32;
#pragma unroll
            for (int ks = 0; ks < 4; ++ks) {
                const int k0 = ks * 8;
                uint32_t a0[4], a1[4];
                a0[0] = Hc[(g     ) * HSTR + k0 + tg    ];
                a0[1] = Hc[(g +  8) * HSTR + k0 + tg    ];
                a0[2] = Hc[(g     ) * HSTR + k0 + tg + 4];
                a0[3] = Hc[(g +  8) * HSTR + k0 + tg + 4];
                a1[0] = Hc[(g + 16) * HSTR + k0 + tg    ];
                a1[1] = Hc[(g + 24) * HSTR + k0 + tg    ];
                a1[2] = Hc[(g + 16) * HSTR + k0 + tg + 4];
                a1[3] = Hc[(g + 24) * HSTR + k0 + tg + 4];
                const int wk = kq * 256 + c * 32 + k0 + tg;
#pragma unroll
                for (int nt = 0; nt < 3; ++nt) {
                    const uint32_t b0 = Ws[(nt * 8 + g) * WSTR + wk    ];
                    const uint32_t b1 = Ws[(nt * 8 + g) * WSTR + wk + 4];
                    mma_tf32(acc[0][nt], a0[0], a0[1], a0[2], a0[3], b0, b1);
                    mma_tf32(acc[1][nt], a1[0], a1[1], a1[2], a1[3], b0, b1);
                }
            }
            if (c + 1 < 8) {
                uint32_t* dst = Hw + ((c + 1) & 1) * WBUF_U32;
                if (c & 1) {
#pragma unroll
                    for (int i = 0; i < 8; ++i) {
                        uint4 pv = make_uint4(f2tf(rb[i].x), f2tf(rb[i].y),
                                              f2tf(rb[i].z), f2tf(rb[i].w));
                        *(uint4*)(dst + (lrow + i * 4) * HSTR + lq8 * 4) = pv;
                    }
                } else {
#pragma unroll
                    for (int i = 0; i < 8; ++i) {
                        uint4 pv = make_uint4(f2tf(ra[i].x), f2tf(ra[i].y),
                                              f2tf(ra[i].z), f2tf(ra[i].w));
                        *(uint4*)(dst + (lrow + i * 4) * HSTR + lq8 * 4) = pv;
                    }
                }
                __syncwarp();
            }
        }

        // ---- write k-quarter partials to dedicated region (warp-private) ----
        {
            const int base = ((kq * 2 + mg) * 32 + lane) * 7;
#pragma unroll
            for (int mt = 0; mt < 2; ++mt)
#pragma unroll
                for (int nt = 0; nt < 3; ++nt)
                    red4[base + mt * 3 + nt] =
                        make_float4(acc[mt][nt][0], acc[mt][nt][1],
                                    acc[mt][nt][2], acc[mt][nt][3]);
        }
        __syncthreads();

        // ---- gather + gates: all 256 threads, one float2 each ----
        {
            float2 s[3];
#pragma unroll
            for (int nt = 0; nt < 3; ++nt)
                s[nt] = red2[((mg_o * 32 + lane2) * 7 + mt_o * 3 + nt) * 2 + hi];
#pragma unroll
            for (int q = 1; q < 4; ++q)
#pragma unroll
                for (int nt = 0; nt < 3; ++nt) {
                    float2 p = red2[(((q * 2 + mg_o) * 32 + lane2) * 7
                                     + mt_o * 3 + nt) * 2 + hi];
                    s[nt].x += p.x; s[nt].y += p.y;
                }

            const float rx = fsig(gi_r.x + s[0].x + bhr.x);
            const float ry = fsig(gi_r.y + s[0].y + bhr.y);
            const float zx = fsig(gi_z.x + s[1].x + bhz.x);
            const float zy = fsig(gi_z.y + s[1].y + bhz.y);
            const float nx = ftanh(gi_n.x + rx * (s[2].x + bhn.x));
            const float ny = ftanh(gi_n.y + ry * (s[2].y + bhn.y));

            float2 hv = make_float2((1.0f - zx) * nx + zx * hprev.x,
                                    (1.0f - zy) * ny + zy * hprev.y);
            hprev = hv;

            float* y_t = y + (size_t)t * BATCH * HID;
            *(float2*)(h_out + m * HID + col) = hv;
            *(float2*)(y_t + m * HID + col)   = hv;
            if (t == TSTEPS - 1)
                *(float2*)(hn + m * HID + col) = hv;

            if (t + 1 < TSTEPS) {
                const float* gim = gi_base + (size_t)(t + 1) * BATCH * G3
                                 + (size_t)m * G3;
                gi_r = ldcs2(gim + col);
                gi_z = ldcs2(gim + HID + col);
                gi_n = ldcs2(gim + 2 * HID + col);
            }
        }

        grid_bar(t, nb);
    }
}

__global__ void bar_reset() {
    g_cnt[0] = 0u;
    g_cnt[1] = 0u;
}

// ============================================================================
// Launcher: 6-node graph.
// ============================================================================
extern "C" void kernel_launch(void* const* d_in, const int* in_sizes, int n_in,
                              void* d_out, int out_size)
{
    const float* x      = (const float*)d_in[0];
    const float* hx     = (const float*)d_in[1];
    const float* w_ih_0 = (const float*)d_in[2];
    const float* w_hh_0 = (const float*)d_in[3];
    const float* b_ih_0 = (const float*)d_in[4];
    const float* b_hh_0 = (const float*)d_in[5];
    const float* w_ih_1 = (const float*)d_in[6];
    const float* w_hh_1 = (const float*)d_in[7];
    const float* b_ih_1 = (const float*)d_in[8];
    const float* b_hh_1 = (const float*)d_in[9];

    float* out = (float*)d_out;
    float* hn0 = out + (size_t)MROWS * HID;
    float* hn1 = hn0 + (size_t)BATCH * HID;

    float *gi, *y0, *ha, *hb;
    cudaGetSymbolAddress((void**)&gi, g_gi);
    cudaGetSymbolAddress((void**)&y0, g_y0);
    cudaGetSymbolAddress((void**)&ha, g_ha);
    cudaGetSymbolAddress((void**)&hb, g_hb);

    cudaFuncSetAttribute(gru_rec, cudaFuncAttributeMaxDynamicSharedMemorySize,
                         RSM_U32 * 4);

    dim3 ggrid(G3 / GBN, MROWS / GBM);  // (24, 256)

    // ---- layer 0 ----
    gemm_tn_bias<<<ggrid, 256>>>(x, w_ih_0, b_ih_0, gi, HID, G3);
    gru_rec<<<RBLK, RTHR, RSM_U32 * 4>>>(gi, hx, w_hh_0, b_hh_0,
                                         ha, hb, y0, hn0);
    bar_reset<<<1, 1>>>();

    // ---- layer 1 ----
    gemm_tn_bias<<<ggrid, 256>>>(y0, w_ih_1, b_ih_1, gi, HID, G3);
    gru_rec<<<RBLK, RTHR, RSM_U32 * 4>>>(gi, hx + (size_t)BATCH * HID,
                                         w_hh_1, b_hh_1,
                                         ha, hb, out, hn1);
    bar_reset<<<1, 1>>>();

    (void)in_sizes; (void)n_in; (void)out_size;
}